// round 7
// baseline (speedup 1.0000x reference)
#include <cuda_runtime.h>
#include <cstdint>

#define BB 1024
#define TT 4096
#define SS 8
#define EE 8
#define PHS 64              // scan steps per cp.async phase
#define NPH (TT / PHS)
#define CPB 8               // chains per block (2 warps x 4 chains)
#define THREADS 64

// Scratch (no cudaMalloc allowed)
__device__ float g_preds[(size_t)BB * TT * SS];   // 134 MB trajectory
__device__ float g_dt[TT];

using ull = unsigned long long;

// ---------------- f32x2 packed helpers ----------------
__device__ __forceinline__ ull pk2(float lo, float hi) {
    ull r; asm("mov.b64 %0, {%1, %2};" : "=l"(r) : "f"(lo), "f"(hi)); return r;
}
__device__ __forceinline__ void up2(ull a, float& lo, float& hi) {
    asm("mov.b64 {%0, %1}, %2;" : "=f"(lo), "=f"(hi) : "l"(a));
}
__device__ __forceinline__ ull fma2(ull a, ull b, ull c) {
    ull r; asm("fma.rn.f32x2 %0, %1, %2, %3;" : "=l"(r) : "l"(a), "l"(b), "l"(c)); return r;
}
__device__ __forceinline__ ull mul2(ull a, ull b) {
    ull r; asm("mul.rn.f32x2 %0, %1, %2;" : "=l"(r) : "l"(a), "l"(b)); return r;
}
__device__ __forceinline__ ull add2(ull a, ull b) {
    ull r; asm("add.rn.f32x2 %0, %1, %2;" : "=l"(r) : "l"(a), "l"(b)); return r;
}

// tanh(x) = 1 - 2/(e^{2x}+1) via ex2.approx + rcp.approx (~1e-7 rel err)
__device__ __forceinline__ float fast_tanh(float z) {
    float e; asm("ex2.approx.f32 %0, %1;" : "=f"(e) : "f"(z * 2.8853900817779268f));
    float r; asm("rcp.approx.f32 %0, %1;" : "=f"(r) : "f"(e + 1.0f));
    return fmaf(-2.0f, r, 1.0f);
}

__device__ __forceinline__ void cpa16(void* dst, const void* src) {
    unsigned s = (unsigned)__cvta_generic_to_shared(dst);
    asm volatile("cp.async.cg.shared.global [%0], [%1], 16;" :: "r"(s), "l"(src));
}

// ---------------------------------------------------------------------------
__global__ void dt_kernel(const float* __restrict__ t) {
    int i = blockIdx.x * blockDim.x + threadIdx.x;
    if (i < TT) g_dt[i] = (i < TT - 1) ? (t[i + 1] - t[i]) : 0.0f;
}

// ---------------------------------------------------------------------------
// Sequential Euler scan: 8 lanes per chain, 4 chains per warp, 2 warps/block.
// Lane u (=lane&7) owns hidden units j = u + 8m, m = 0..3.
// Exogenous part c[m] = br1[j] + e.We[:,j] is software-pipelined one step ahead
// so its issue lands in the butterfly's latency hole.
__global__ __launch_bounds__(THREADS, 1)
void scan_kernel(const float* __restrict__ x,    // [B,T,E]
                 const float* __restrict__ y0,   // [B,S]
                 const float* __restrict__ Wr1,  // [S+E, 32]
                 const float* __restrict__ br1,  // [32]
                 const float* __restrict__ Wr2,  // [32, S]
                 const float* __restrict__ br2)  // [S]
{
    __shared__ __align__(16) float sx[2][CPB][PHS * EE];  // 32 KB x-staging
    __shared__ __align__(16) float sdt[2][PHS];           // dt staging

    const int tid  = threadIdx.x;
    const int lane = tid & 31;
    const int w    = tid >> 5;
    const int u    = lane & 7;                         // lane within 8-group
    const int cloc = w * 4 + (lane >> 3);              // chain slot in block
    const int chain = blockIdx.x * CPB + cloc;

    // ---- register-resident weights (packed pairs), units j = u + 8m ----
    ull wy[4][4], we[4][4], w2p[4][4], b1p[4];
#pragma unroll
    for (int m = 0; m < 4; ++m) {
        const int j = u + 8 * m;
#pragma unroll
        for (int k = 0; k < 4; ++k) {
            wy[m][k]  = pk2(Wr1[(2 * k) * 32 + j],     Wr1[(2 * k + 1) * 32 + j]);
            we[m][k]  = pk2(Wr1[(8 + 2 * k) * 32 + j], Wr1[(9 + 2 * k) * 32 + j]);
            w2p[m][k] = pk2(Wr2[j * 8 + 2 * k],        Wr2[j * 8 + 2 * k + 1]);
        }
        b1p[m] = pk2(br1[j], 0.0f);       // bias in lo slot; hi stays 0 through the e-chain
    }
    ull b2p[4];
#pragma unroll
    for (int k = 0; k < 4; ++k) b2p[k] = pk2(br2[2 * k], br2[2 * k + 1]);

    // ---- initial state (replicated per lane, 4 packed pairs) ----
    ull yp[4];
    {
        const float4* q = (const float4*)(y0 + (size_t)chain * SS);
        float4 A = q[0], B = q[1];
        yp[0] = pk2(A.x, A.y); yp[1] = pk2(A.z, A.w);
        yp[2] = pk2(B.x, B.y); yp[3] = pk2(B.z, B.w);
    }

    // ---- phase staging: 8 chains x 512 floats = 1024 x 16B; 16 per thread ----
    auto issue = [&](int ph, int buf) {
#pragma unroll
        for (int q = 0; q < 16; ++q) {
            const int idx = tid + q * 64;         // 0..1023
            const int c   = idx >> 7;             // chain
            const int off = idx & 127;            // 16B chunk within chain
            cpa16(&sx[buf][c][off * 4],
                  x + ((size_t)(blockIdx.x * CPB + c) * TT + (size_t)ph * PHS) * EE + off * 4);
        }
        if (tid < 16) cpa16(&sdt[buf][tid * 4], g_dt + ph * PHS + tid * 4);
        asm volatile("cp.async.commit_group;");
    };

    // c[m] = b1 + e.We for a given step's e (two LDS.64 + 16 fma2)
    auto edot = [&](const float* eb, int i, ull c[4]) {
        const ull* ep = (const ull*)(eb + i * 8);   // e already packed pairwise in smem
        const ull e0 = ep[0], e1 = ep[1], e2 = ep[2], e3 = ep[3];
#pragma unroll
        for (int m = 0; m < 4; ++m) {
            ull t0 = fma2(e0, we[m][0], b1p[m]);
            t0 = fma2(e1, we[m][1], t0);
            t0 = fma2(e2, we[m][2], t0);
            c[m] = fma2(e3, we[m][3], t0);
        }
    };

    issue(0, 0);
    asm volatile("cp.async.wait_group 0;");
    __syncthreads();

    float* pp = g_preds + (size_t)chain * TT * SS;
    int buf = 0;

    ull c[4];
    edot(sx[buf][cloc], 0, c);          // prologue: step 0's exogenous part
    float dtcur = sdt[buf][0];

    for (int ph = 0; ph < NPH; ++ph) {
        if (ph + 1 < NPH) {
            issue(ph + 1, buf ^ 1);
            asm volatile("cp.async.wait_group 1;");
        }
        __syncthreads();
        const float* eb  = sx[buf][cloc];
        const float* dtb = sdt[buf];

#pragma unroll 2
        for (int i = 0; i < PHS; ++i) {
            // z_j = c[m] + y.Wy  ;  h = tanh(z)   (bias already inside c)
            float h[4];
#pragma unroll
            for (int m = 0; m < 4; ++m) {
                ull a = fma2(yp[0], wy[m][0], c[m]);
                a = fma2(yp[1], wy[m][1], a);
                a = fma2(yp[2], wy[m][2], a);
                a = fma2(yp[3], wy[m][3], a);
                float lo, hi; up2(a, lo, hi);
                h[m] = fast_tanh(lo + hi);
            }

            // partial rhs pairs over the 4 owned units
            ull h2[4];
#pragma unroll
            for (int m = 0; m < 4; ++m) h2[m] = pk2(h[m], h[m]);
            ull p[4];
#pragma unroll
            for (int sp = 0; sp < 4; ++sp) {
                ull t0 = mul2(h2[0], w2p[0][sp]);
                t0 = fma2(h2[1], w2p[1][sp], t0);
                t0 = fma2(h2[2], w2p[2][sp], t0);
                p[sp] = fma2(h2[3], w2p[3][sp], t0);
            }

            // ---- latency hole fill: store preds (pre-update y), prefetch
            //      next step's exogenous part + dt while the butterfly drains ----
            if (u == 0) {
                float f0, f1, f2, f3, f4, f5, f6, f7;
                up2(yp[0], f0, f1); up2(yp[1], f2, f3);
                up2(yp[2], f4, f5); up2(yp[3], f6, f7);
                float4* o = (float4*)pp;
                o[0] = make_float4(f0, f1, f2, f3);
                o[1] = make_float4(f4, f5, f6, f7);
            }
            pp += SS;

            const float dtv = dtcur;
            if (i + 1 < PHS) {
                edot(eb, i + 1, c);          // independent of y — fills SHFL waits
                dtcur = dtb[i + 1];
            }

            // 3-round butterfly all-reduce within the 8-lane group (64-bit shfl)
#pragma unroll
            for (int mask = 1; mask < 8; mask <<= 1) {
#pragma unroll
                for (int sp = 0; sp < 4; ++sp)
                    p[sp] = add2(p[sp], __shfl_xor_sync(0xffffffffu, p[sp], mask));
            }

            // Euler update (dt[T-1]=0 makes the final update a no-op)
            const ull dt2 = pk2(dtv, dtv);
#pragma unroll
            for (int sp = 0; sp < 4; ++sp)
                yp[sp] = fma2(dt2, add2(p[sp], b2p[sp]), yp[sp]);
        }
        __syncthreads();     // all reads of sx[buf] done before next issue overwrites it
        buf ^= 1;
        if (ph + 1 < NPH) {  // prologue for the next phase's first step
            edot(sx[buf][cloc], 0, c);
            dtcur = sdt[buf][0];
        }
    }
}

// ---------------------------------------------------------------------------
// Head: out = relu(preds @ W1 + b1) @ W2 + b2 — fully register-resident weights
__global__ __launch_bounds__(256)
void head_kernel(const float* __restrict__ W1, const float* __restrict__ b1,
                 const float* __restrict__ W2, const float* __restrict__ b2,
                 float* __restrict__ out)
{
    float w1[8][10], bb1[10], w2[10][2];
#pragma unroll
    for (int s = 0; s < 8; ++s)
#pragma unroll
        for (int i = 0; i < 10; ++i) w1[s][i] = __ldg(&W1[s * 10 + i]);
#pragma unroll
    for (int i = 0; i < 10; ++i) {
        bb1[i]   = __ldg(&b1[i]);
        w2[i][0] = __ldg(&W2[i * 2 + 0]);
        w2[i][1] = __ldg(&W2[i * 2 + 1]);
    }
    const float c0 = __ldg(&b2[0]), c1 = __ldg(&b2[1]);

    const int nt  = gridDim.x * blockDim.x;
    const int tid = blockIdx.x * blockDim.x + threadIdx.x;
    const int NPOS = BB * TT;

    for (int pos = tid; pos < NPOS; pos += nt) {
        const float4* ypt = (const float4*)(g_preds + (size_t)pos * SS);
        const float4 A = ypt[0], B = ypt[1];
        const float yv[8] = {A.x, A.y, A.z, A.w, B.x, B.y, B.z, B.w};
        float o0 = c0, o1 = c1;
#pragma unroll
        for (int i = 0; i < 10; ++i) {
            float hz = bb1[i];
#pragma unroll
            for (int s = 0; s < 8; ++s) hz = fmaf(yv[s], w1[s][i], hz);
            hz = fmaxf(hz, 0.0f);
            o0 = fmaf(hz, w2[i][0], o0);
            o1 = fmaf(hz, w2[i][1], o1);
        }
        *(float2*)(out + (size_t)pos * 2) = make_float2(o0, o1);
    }
}

// ---------------------------------------------------------------------------
extern "C" void kernel_launch(void* const* d_in, const int* in_sizes, int n_in,
                              void* d_out, int out_size) {
    const float* x   = (const float*)d_in[0];
    const float* t   = (const float*)d_in[1];
    const float* y0  = (const float*)d_in[2];
    const float* Wr1 = (const float*)d_in[3];
    const float* br1 = (const float*)d_in[4];
    const float* Wr2 = (const float*)d_in[5];
    const float* br2 = (const float*)d_in[6];
    const float* W1  = (const float*)d_in[7];
    const float* b1  = (const float*)d_in[8];
    const float* W2  = (const float*)d_in[9];
    const float* b2  = (const float*)d_in[10];
    float* out = (float*)d_out;

    dt_kernel<<<16, 256>>>(t);
    scan_kernel<<<BB / CPB, THREADS>>>(x, y0, Wr1, br1, Wr2, br2);
    head_kernel<<<2048, 256>>>(W1, b1, W2, b2, out);
}

// round 8
// speedup vs baseline: 1.1033x; 1.1033x over previous
#include <cuda_runtime.h>
#include <cstdint>

#define BB 1024
#define TT 4096
#define SS 8
#define EE 8
#define PHS 64              // scan steps per cp.async phase
#define NPH (TT / PHS)
#define CPB 8               // chains per block (4 warps x 2 chains)
#define THREADS 128

// Scratch (no cudaMalloc allowed)
__device__ float g_preds[(size_t)BB * TT * SS];   // 134 MB trajectory
__device__ float g_dt[TT];

using ull = unsigned long long;

// ---------------- f32x2 packed helpers ----------------
__device__ __forceinline__ ull pk2(float lo, float hi) {
    ull r; asm("mov.b64 %0, {%1, %2};" : "=l"(r) : "f"(lo), "f"(hi)); return r;
}
__device__ __forceinline__ void up2(ull a, float& lo, float& hi) {
    asm("mov.b64 {%0, %1}, %2;" : "=f"(lo), "=f"(hi) : "l"(a));
}
__device__ __forceinline__ ull fma2(ull a, ull b, ull c) {
    ull r; asm("fma.rn.f32x2 %0, %1, %2, %3;" : "=l"(r) : "l"(a), "l"(b), "l"(c)); return r;
}
__device__ __forceinline__ ull mul2(ull a, ull b) {
    ull r; asm("mul.rn.f32x2 %0, %1, %2;" : "=l"(r) : "l"(a), "l"(b)); return r;
}
__device__ __forceinline__ ull add2(ull a, ull b) {
    ull r; asm("add.rn.f32x2 %0, %1, %2;" : "=l"(r) : "l"(a), "l"(b)); return r;
}

// tanh(x) = 1 - 2/(e^{2x}+1) via ex2.approx + rcp.approx (~1e-7 rel err)
__device__ __forceinline__ float fast_tanh(float z) {
    float e; asm("ex2.approx.f32 %0, %1;" : "=f"(e) : "f"(z * 2.8853900817779268f));
    float r; asm("rcp.approx.f32 %0, %1;" : "=f"(r) : "f"(e + 1.0f));
    return fmaf(-2.0f, r, 1.0f);
}

__device__ __forceinline__ void cpa16(void* dst, const void* src) {
    unsigned s = (unsigned)__cvta_generic_to_shared(dst);
    asm volatile("cp.async.cg.shared.global [%0], [%1], 16;" :: "r"(s), "l"(src));
}

// ---------------------------------------------------------------------------
__global__ void dt_kernel(const float* __restrict__ t) {
    int i = blockIdx.x * blockDim.x + threadIdx.x;
    if (i < TT) g_dt[i] = (i < TT - 1) ? (t[i + 1] - t[i]) : 0.0f;
}

// ---------------------------------------------------------------------------
// Sequential Euler scan: 16 lanes per chain, 2 chains per warp, 4 warps/block.
// Lane u (=lane&15) owns hidden units j = u and j = u+16.
__global__ __launch_bounds__(THREADS, 1)
void scan_kernel(const float* __restrict__ x,    // [B,T,E]
                 const float* __restrict__ y0,   // [B,S]
                 const float* __restrict__ Wr1,  // [S+E, 32]
                 const float* __restrict__ br1,  // [32]
                 const float* __restrict__ Wr2,  // [32, S]
                 const float* __restrict__ br2)  // [S]
{
    __shared__ __align__(16) float sx[2][CPB][PHS * EE];  // 32 KB x-staging
    __shared__ __align__(16) float sdt[2][PHS];           // dt staging

    const int tid  = threadIdx.x;
    const int lane = tid & 31;
    const int wid  = tid >> 5;
    const int u    = lane & 15;                        // lane within 16-group
    const int grp  = lane >> 4;                        // chain within warp
    const int cloc = wid * 2 + grp;                    // chain slot in block
    const int chain = blockIdx.x * CPB + cloc;

    // ---- register-resident weights (packed pairs), units j = u + 16m ----
    ull wy[2][4], we[2][4], w2p[2][4], b1p[2];
#pragma unroll
    for (int m = 0; m < 2; ++m) {
        const int j = u + 16 * m;
#pragma unroll
        for (int k = 0; k < 4; ++k) {
            wy[m][k]  = pk2(Wr1[(2 * k) * 32 + j],     Wr1[(2 * k + 1) * 32 + j]);
            we[m][k]  = pk2(Wr1[(8 + 2 * k) * 32 + j], Wr1[(9 + 2 * k) * 32 + j]);
            w2p[m][k] = pk2(Wr2[j * 8 + 2 * k],        Wr2[j * 8 + 2 * k + 1]);
        }
        b1p[m] = pk2(br1[j], 0.0f);     // bias in lo slot; hi stays 0 through the chain
    }
    ull b2p[4];
#pragma unroll
    for (int k = 0; k < 4; ++k) b2p[k] = pk2(br2[2 * k], br2[2 * k + 1]);

    // ---- initial state (replicated per lane, 4 packed pairs) ----
    ull yp[4];
    {
        const float4* q = (const float4*)(y0 + (size_t)chain * SS);
        float4 A = q[0], B = q[1];
        yp[0] = pk2(A.x, A.y); yp[1] = pk2(A.z, A.w);
        yp[2] = pk2(B.x, B.y); yp[3] = pk2(B.z, B.w);
    }

    // ---- phase staging: 8 chains x 512 floats = 1024 x 16B; 8 per thread ----
    auto issue = [&](int ph, int buf) {
#pragma unroll
        for (int q = 0; q < 8; ++q) {
            const int idx = tid + q * THREADS;    // 0..1023
            const int c   = idx >> 7;             // chain
            const int off = idx & 127;            // 16B chunk within chain
            cpa16(&sx[buf][c][off * 4],
                  x + ((size_t)(blockIdx.x * CPB + c) * TT + (size_t)ph * PHS) * EE + off * 4);
        }
        if (tid < 16) cpa16(&sdt[buf][tid * 4], g_dt + ph * PHS + tid * 4);
        asm volatile("cp.async.commit_group;");
    };

    issue(0, 0);
    asm volatile("cp.async.wait_group 0;");
    __syncthreads();

    float* pp = g_preds + (size_t)chain * TT * SS;
    int buf = 0;

    for (int ph = 0; ph < NPH; ++ph) {
        if (ph + 1 < NPH) {
            issue(ph + 1, buf ^ 1);
            asm volatile("cp.async.wait_group 1;");
        }
        __syncthreads();
        const float* eb  = sx[buf][cloc];
        const float* dtb = sdt[buf];

#pragma unroll 2
        for (int i = 0; i < PHS; ++i) {
            // preds[b][t] = state BEFORE this step's update (preds[0] = y0)
            if (u == 0) {
                float f0, f1, f2, f3, f4, f5, f6, f7;
                up2(yp[0], f0, f1); up2(yp[1], f2, f3);
                up2(yp[2], f4, f5); up2(yp[3], f6, f7);
                float4* o = (float4*)pp;
                o[0] = make_float4(f0, f1, f2, f3);
                o[1] = make_float4(f4, f5, f6, f7);
            }
            pp += SS;

            const float dt = dtb[i];
            const ull* ep = (const ull*)(eb + i * 8);
            const ull e0 = ep[0], e1 = ep[1], e2 = ep[2], e3 = ep[3];

            // z_j = br1 + e.We + y.Wy for the 2 owned units; h = tanh(z)
            float h[2];
#pragma unroll
            for (int m = 0; m < 2; ++m) {
                ull c = fma2(e0, we[m][0], b1p[m]);
                c = fma2(e1, we[m][1], c);
                c = fma2(e2, we[m][2], c);
                c = fma2(e3, we[m][3], c);
                ull a = fma2(yp[0], wy[m][0], c);
                a = fma2(yp[1], wy[m][1], a);
                a = fma2(yp[2], wy[m][2], a);
                a = fma2(yp[3], wy[m][3], a);
                float lo, hi; up2(a, lo, hi);
                h[m] = fast_tanh(lo + hi);
            }

            // partial rhs pairs over the 2 owned units
            const ull h0d = pk2(h[0], h[0]);
            const ull h1d = pk2(h[1], h[1]);
            ull p[4];
#pragma unroll
            for (int sp = 0; sp < 4; ++sp)
                p[sp] = fma2(h1d, w2p[1][sp], mul2(h0d, w2p[0][sp]));

            // 4-round butterfly all-reduce within the 16-lane group (64-bit shfl)
#pragma unroll
            for (int mask = 1; mask < 16; mask <<= 1) {
#pragma unroll
                for (int sp = 0; sp < 4; ++sp)
                    p[sp] = add2(p[sp], __shfl_xor_sync(0xffffffffu, p[sp], mask));
            }

            // Euler update (dt[T-1]=0 makes the final update a no-op)
            const ull dt2 = pk2(dt, dt);
#pragma unroll
            for (int sp = 0; sp < 4; ++sp)
                yp[sp] = fma2(dt2, add2(p[sp], b2p[sp]), yp[sp]);
        }
        __syncthreads();     // all reads of sx[buf] done before next issue overwrites it
        buf ^= 1;
    }
}

// ---------------------------------------------------------------------------
// Head: out = relu(preds @ W1 + b1) @ W2 + b2 — fully register-resident weights
__global__ __launch_bounds__(256)
void head_kernel(const float* __restrict__ W1, const float* __restrict__ b1,
                 const float* __restrict__ W2, const float* __restrict__ b2,
                 float* __restrict__ out)
{
    float w1[8][10], bb1[10], w2[10][2];
#pragma unroll
    for (int s = 0; s < 8; ++s)
#pragma unroll
        for (int i = 0; i < 10; ++i) w1[s][i] = __ldg(&W1[s * 10 + i]);
#pragma unroll
    for (int i = 0; i < 10; ++i) {
        bb1[i]   = __ldg(&b1[i]);
        w2[i][0] = __ldg(&W2[i * 2 + 0]);
        w2[i][1] = __ldg(&W2[i * 2 + 1]);
    }
    const float c0 = __ldg(&b2[0]), c1 = __ldg(&b2[1]);

    const int nt  = gridDim.x * blockDim.x;
    const int tid = blockIdx.x * blockDim.x + threadIdx.x;
    const int NPOS = BB * TT;

    for (int pos = tid; pos < NPOS; pos += nt) {
        const float4* ypt = (const float4*)(g_preds + (size_t)pos * SS);
        const float4 A = ypt[0], B = ypt[1];
        const float yv[8] = {A.x, A.y, A.z, A.w, B.x, B.y, B.z, B.w};
        float o0 = c0, o1 = c1;
#pragma unroll
        for (int i = 0; i < 10; ++i) {
            float hz = bb1[i];
#pragma unroll
            for (int s = 0; s < 8; ++s) hz = fmaf(yv[s], w1[s][i], hz);
            hz = fmaxf(hz, 0.0f);
            o0 = fmaf(hz, w2[i][0], o0);
            o1 = fmaf(hz, w2[i][1], o1);
        }
        *(float2*)(out + (size_t)pos * 2) = make_float2(o0, o1);
    }
}

// ---------------------------------------------------------------------------
extern "C" void kernel_launch(void* const* d_in, const int* in_sizes, int n_in,
                              void* d_out, int out_size) {
    const float* x   = (const float*)d_in[0];
    const float* t   = (const float*)d_in[1];
    const float* y0  = (const float*)d_in[2];
    const float* Wr1 = (const float*)d_in[3];
    const float* br1 = (const float*)d_in[4];
    const float* Wr2 = (const float*)d_in[5];
    const float* br2 = (const float*)d_in[6];
    const float* W1  = (const float*)d_in[7];
    const float* b1  = (const float*)d_in[8];
    const float* W2  = (const float*)d_in[9];
    const float* b2  = (const float*)d_in[10];
    float* out = (float*)d_out;

    dt_kernel<<<16, 256>>>(t);
    scan_kernel<<<BB / CPB, THREADS>>>(x, y0, Wr1, br1, Wr2, br2);
    head_kernel<<<2048, 256>>>(W1, b1, W2, b2, out);
}